// round 1
// baseline (speedup 1.0000x reference)
#include <cuda_runtime.h>
#include <math.h>

// Problem constants (fixed shapes from reference setup_inputs)
#define BB   2
#define LL   2048
#define DM   1024
#define DI   2048
#define MTOT (BB*LL)      // 4096 rows
#define NST  16
#define DTR  64
#define XDN  96           // dt_rank + 2*d_state
#define SPLITK 8

// Scratch (device globals; no runtime allocation allowed)
__device__ float g_xz  [(size_t)MTOT * 2 * DI];        // 64 MB  [4096][4096] (cols 0..2047=xb, 2048..4095=z)
__device__ float g_xb  [(size_t)MTOT * DI];            // 32 MB  conv+silu output
__device__ float g_xdp [(size_t)SPLITK * MTOT * XDN];  // 12 MB  split-K partials
__device__ float g_xdbl[(size_t)MTOT * XDN];           // 1.5 MB
__device__ float g_dt  [(size_t)MTOT * DI];            // 32 MB
__device__ float g_yg  [(size_t)MTOT * DI];            // 32 MB  gated scan output

__device__ __forceinline__ float softplus_f(float v) {
    return v > 20.f ? v : log1pf(__expf(v));
}
__device__ __forceinline__ float silu_f(float v) {
    return v / (1.f + __expf(-v));
}

// ---------------------------------------------------------------------------
// Generic fp32 GEMM: C[M,N] = A[M,K(lda)] * B[K,N(ldb)]
// 128x128 block tile, BK=16, 256 threads, 8x8 per-thread microtile.
// EPI: 0 = plain store, 2 = softplus(acc + bias[col]), 3 = split-K partial store
// Requirements: M % 128 == 0, kChunk % 16 == 0, N % 4 == 0, 16B-aligned rows.
// ---------------------------------------------------------------------------
template<int EPI>
__global__ void __launch_bounds__(256) sgemm128(
    const float* __restrict__ A, const float* __restrict__ B,
    float* __restrict__ C, const float* __restrict__ bias,
    int M, int N, int K, int lda, int ldb, int ldc, int kChunk)
{
    __shared__ float As[16][128];   // [k][m]
    __shared__ float Bs[16][128];   // [k][n]

    const int tid = threadIdx.x;
    const int m0 = blockIdx.y * 128;
    const int n0 = blockIdx.x * 128;
    const int k0 = blockIdx.z * kChunk;
    int kEnd = k0 + kChunk; if (kEnd > K) kEnd = K;

    float acc[8][8];
#pragma unroll
    for (int i = 0; i < 8; i++)
#pragma unroll
        for (int j = 0; j < 8; j++) acc[i][j] = 0.f;

    const int tr = tid >> 4;          // 0..15
    const int tc = tid & 15;          // 0..15
    const int arow = tid >> 2;        // 0..63
    const int acol = (tid & 3) * 4;   // 0,4,8,12
    const int brow = tid >> 5;        // 0..7
    const int bcol = (tid & 31) * 4;  // 0..124

    for (int kt = k0; kt < kEnd; kt += 16) {
        __syncthreads();
        // A tile: 128x16, store transposed As[k][m]
#pragma unroll
        for (int rr = 0; rr < 2; rr++) {
            int row = arow + rr * 64;
            const float4 v = *(const float4*)(A + (size_t)(m0 + row) * lda + kt + acol);
            As[acol + 0][row] = v.x;
            As[acol + 1][row] = v.y;
            As[acol + 2][row] = v.z;
            As[acol + 3][row] = v.w;
        }
        // B tile: 16x128 direct
#pragma unroll
        for (int rr = 0; rr < 2; rr++) {
            int row = brow + rr * 8;
            float4 v = make_float4(0.f, 0.f, 0.f, 0.f);
            if (n0 + bcol < N)
                v = *(const float4*)(B + (size_t)(kt + row) * ldb + n0 + bcol);
            *(float4*)&Bs[row][bcol] = v;
        }
        __syncthreads();

#pragma unroll
        for (int k = 0; k < 16; k++) {
            float a[8], b[8];
            *(float4*)&a[0] = *(const float4*)&As[k][tr * 8];
            *(float4*)&a[4] = *(const float4*)&As[k][tr * 8 + 4];
            *(float4*)&b[0] = *(const float4*)&Bs[k][tc * 8];
            *(float4*)&b[4] = *(const float4*)&Bs[k][tc * 8 + 4];
#pragma unroll
            for (int i = 0; i < 8; i++)
#pragma unroll
                for (int j = 0; j < 8; j++)
                    acc[i][j] = fmaf(a[i], b[j], acc[i][j]);
        }
    }

    const size_t zoff = (EPI == 3) ? (size_t)blockIdx.z * (size_t)M * ldc : 0;
#pragma unroll
    for (int i = 0; i < 8; i++) {
        const int row = m0 + tr * 8 + i;
#pragma unroll
        for (int jj = 0; jj < 8; jj += 4) {
            const int col = n0 + tc * 8 + jj;
            if (col < N) {
                float4 v;
                v.x = acc[i][jj + 0]; v.y = acc[i][jj + 1];
                v.z = acc[i][jj + 2]; v.w = acc[i][jj + 3];
                if (EPI == 2) {
                    const float4 bb = *(const float4*)(bias + col);
                    v.x = softplus_f(v.x + bb.x);
                    v.y = softplus_f(v.y + bb.y);
                    v.z = softplus_f(v.z + bb.z);
                    v.w = softplus_f(v.w + bb.w);
                }
                *(float4*)(C + zoff + (size_t)row * ldc + col) = v;
            }
        }
    }
}

// ---------------------------------------------------------------------------
// Causal depthwise conv (k=4) + bias + SiLU. Reads xb half of g_xz, writes g_xb.
// ---------------------------------------------------------------------------
__global__ void conv_silu_kernel(const float* __restrict__ conv_w,
                                 const float* __restrict__ conv_b)
{
    const int t = blockIdx.x * 256 + threadIdx.x;
    if (t >= MTOT * (DI / 4)) return;
    const int d4 = t & (DI / 4 - 1);
    const int r  = t >> 9;             // DI/4 = 512
    const int l  = r & (LL - 1);
    const int d  = d4 * 4;

    const float4 b4 = *(const float4*)(conv_b + d);
    float ax = b4.x, ay = b4.y, az = b4.z, aw = b4.w;
#pragma unroll
    for (int k = 0; k < 4; k++) {
        const int ls = l - 3 + k;
        if (ls >= 0) {
            const float4 v = *(const float4*)(g_xz + (size_t)(r - 3 + k) * (2 * DI) + d);
            ax = fmaf(v.x, conv_w[(d + 0) * 4 + k], ax);
            ay = fmaf(v.y, conv_w[(d + 1) * 4 + k], ay);
            az = fmaf(v.z, conv_w[(d + 2) * 4 + k], az);
            aw = fmaf(v.w, conv_w[(d + 3) * 4 + k], aw);
        }
    }
    float4 o;
    o.x = silu_f(ax); o.y = silu_f(ay); o.z = silu_f(az); o.w = silu_f(aw);
    *(float4*)(g_xb + (size_t)r * DI + d) = o;
}

// Deterministic split-K reduction for x_dbl
__global__ void reduce_xdbl_kernel()
{
    const int i = blockIdx.x * 256 + threadIdx.x;
    if (i >= MTOT * XDN) return;
    float s = 0.f;
#pragma unroll
    for (int z = 0; z < SPLITK; z++)
        s += g_xdp[(size_t)z * MTOT * XDN + i];
    g_xdbl[i] = s;
}

// ---------------------------------------------------------------------------
// Selective scan. 16 lanes per (b,d) channel (one state per lane), serial in L.
// Fused epilogue: yg = (scan_y + xb*D) * silu(z)
// ---------------------------------------------------------------------------
__global__ void __launch_bounds__(256) scan_kernel(const float* __restrict__ A_log,
                                                   const float* __restrict__ Dvec)
{
    const int tid = threadIdx.x;
    const int grp = tid >> 4;                 // 0..15 channels per block
    const int n   = tid & 15;                 // state index
    const int c   = blockIdx.x * 16 + grp;    // channel 0..4095
    const int b   = c >> 11;
    const int d   = c & (DI - 1);

    const float a  = -__expf(A_log[d * NST + n]);
    const float Dd = Dvec[d];

    const size_t r0 = (size_t)b << 11;        // base row for this batch
    const float* dtp = g_dt   + r0 * DI + d;
    const float* xbp = g_xb   + r0 * DI + d;
    const float* zp  = g_xz   + r0 * (2 * DI) + DI + d;
    const float* bcp = g_xdbl + r0 * XDN + DTR + n;   // B at +0, C at +NST
    float*       yp  = g_yg   + r0 * DI + d;

    float h = 0.f;
    for (int l = 0; l < LL; l++) {
        const float dtv = dtp[(size_t)l * DI];
        const float xv  = xbp[(size_t)l * DI];
        const float Bn  = bcp[(size_t)l * XDN];
        const float Cn  = bcp[(size_t)l * XDN + NST];
        const float dA  = __expf(a * dtv);
        h = fmaf(h, dA, xv * dtv * Bn);
        float y = h * Cn;
        y += __shfl_xor_sync(0xffffffffu, y, 1);
        y += __shfl_xor_sync(0xffffffffu, y, 2);
        y += __shfl_xor_sync(0xffffffffu, y, 4);
        y += __shfl_xor_sync(0xffffffffu, y, 8);
        if (n == 0) {
            const float zv = zp[(size_t)l * (2 * DI)];
            yp[(size_t)l * DI] = (y + xv * Dd) * silu_f(zv);
        }
    }
}

// ---------------------------------------------------------------------------
extern "C" void kernel_launch(void* const* d_in, const int* in_sizes, int n_in,
                              void* d_out, int out_size)
{
    const float* x      = (const float*)d_in[0];
    const float* W_in   = (const float*)d_in[1];
    const float* conv_w = (const float*)d_in[2];
    const float* conv_b = (const float*)d_in[3];
    const float* W_x    = (const float*)d_in[4];
    const float* W_dt   = (const float*)d_in[5];
    const float* b_dt   = (const float*)d_in[6];
    const float* A_log  = (const float*)d_in[7];
    const float* Dv     = (const float*)d_in[8];
    const float* W_out  = (const float*)d_in[9];
    float* out = (float*)d_out;

    float *xz, *xb, *xdp, *xdbl, *dt, *yg;
    cudaGetSymbolAddress((void**)&xz,   g_xz);
    cudaGetSymbolAddress((void**)&xb,   g_xb);
    cudaGetSymbolAddress((void**)&xdp,  g_xdp);
    cudaGetSymbolAddress((void**)&xdbl, g_xdbl);
    cudaGetSymbolAddress((void**)&dt,   g_dt);
    cudaGetSymbolAddress((void**)&yg,   g_yg);

    // 1) xz = x @ W_in        [4096,1024]x[1024,4096]
    sgemm128<0><<<dim3(32, 32, 1), 256>>>(x, W_in, xz, nullptr,
                                          MTOT, 2 * DI, DM, DM, 2 * DI, 2 * DI, DM);
    // 2) causal conv + SiLU
    conv_silu_kernel<<<(MTOT * (DI / 4)) / 256, 256>>>(conv_w, conv_b);
    // 3) x_dbl = xb @ W_x     [4096,2048]x[2048,96], split-K=8 + deterministic reduce
    sgemm128<3><<<dim3(1, 32, SPLITK), 256>>>(xb, W_x, xdp, nullptr,
                                              MTOT, XDN, DI, DI, XDN, XDN, DI / SPLITK);
    reduce_xdbl_kernel<<<(MTOT * XDN + 255) / 256, 256>>>();
    // 4) dt = softplus(dt_low @ W_dt + b_dt)   [4096,64]x[64,2048]
    sgemm128<2><<<dim3(16, 32, 1), 256>>>(xdbl, W_dt, dt, b_dt,
                                          MTOT, DI, DTR, XDN, DI, DI, DTR);
    // 5) selective scan + gating epilogue
    scan_kernel<<<MTOT / 16, 256>>>(A_log, Dv);
    // 6) out = yg @ W_out     [4096,2048]x[2048,1024]
    sgemm128<0><<<dim3(8, 32, 1), 256>>>(yg, W_out, out, nullptr,
                                         MTOT, DM, DI, DI, DM, DM, DI);
}

// round 3
// speedup vs baseline: 1.2760x; 1.2760x over previous
#include <cuda_runtime.h>
#include <cuda_bf16.h>
#include <math.h>
#include <stdint.h>

#define BB   2
#define LL   2048
#define DM   1024
#define DI   2048
#define MTOT (BB*LL)
#define NST  16
#define DTR  64
#define XDN  96
#define SPLITK 8

__device__ float g_xz  [(size_t)MTOT * 2 * DI];
__device__ float g_xb  [(size_t)MTOT * DI];
__device__ float g_xdp [(size_t)SPLITK * MTOT * XDN];
__device__ float g_xdbl[(size_t)MTOT * XDN];
__device__ float g_dt  [(size_t)MTOT * DI];
__device__ float g_yg  [(size_t)MTOT * DI];
__device__ __nv_bfloat16 g_A1[(size_t)MTOT * 3 * DM];
__device__ __nv_bfloat16 g_B1[(size_t)(2*DI) * 3 * DM];
__device__ __nv_bfloat16 g_A2[(size_t)MTOT * 3 * DI];
__device__ __nv_bfloat16 g_B2[(size_t)DM * 3 * DI];

__device__ __forceinline__ float softplus_f(float v) {
    return v > 20.f ? v : log1pf(__expf(v));
}
__device__ __forceinline__ float silu_f(float v) {
    return v / (1.f + __expf(-v));
}

__device__ __forceinline__ uint32_t smem_u32(const void* p) {
    uint32_t addr;
    asm("{ .reg .u64 tmp; cvta.to.shared.u64 tmp, %1; cvt.u32.u64 %0, tmp; }"
        : "=r"(addr) : "l"(p));
    return addr;
}
__device__ __forceinline__ void cp_async16(uint32_t dst, const void* src) {
    asm volatile("cp.async.cg.shared.global [%0], [%1], 16;" :: "r"(dst), "l"(src));
}
__device__ __forceinline__ void cp_commit() {
    asm volatile("cp.async.commit_group;");
}
template<int N>
__device__ __forceinline__ void cp_wait() {
    asm volatile("cp.async.wait_group %0;" :: "n"(N) : "memory");
}
__device__ __forceinline__ void ldm_x4(uint32_t* r, uint32_t addr) {
    asm volatile("ldmatrix.sync.aligned.m8n8.x4.shared.b16 {%0,%1,%2,%3}, [%4];"
        : "=r"(r[0]), "=r"(r[1]), "=r"(r[2]), "=r"(r[3]) : "r"(addr));
}
__device__ __forceinline__ void mma_bf16(float* c, const uint32_t* a, const uint32_t* b) {
    asm volatile(
        "mma.sync.aligned.m16n8k16.row.col.f32.bf16.bf16.f32 "
        "{%0,%1,%2,%3}, {%4,%5,%6,%7}, {%8,%9}, {%0,%1,%2,%3};"
        : "+f"(c[0]), "+f"(c[1]), "+f"(c[2]), "+f"(c[3])
        : "r"(a[0]), "r"(a[1]), "r"(a[2]), "r"(a[3]), "r"(b[0]), "r"(b[1]));
}

// ---------------------------------------------------------------------------
// bf16 mma.sync GEMM: C[M,N] = A[M,Kp] * B[N,Kp]^T, fp32 accumulate.
// 128x128x32 block tile, 8 warps (2x4), 64x32 warp tiles, cp.async double
// buffer, 80B smem pitch (conflict-free ldmatrix).
// Grid: (N/128, M/128). Dynamic smem = 40960 B.
// ---------------------------------------------------------------------------
#define PITCHB 80          // bytes per smem row (32 bf16 + 8 pad)
#define TILEB  10240       // 128 rows * 80 B
__global__ void __launch_bounds__(256, 2) gemm_mma(
    const __nv_bfloat16* __restrict__ A, const __nv_bfloat16* __restrict__ B,
    float* __restrict__ C, int Kp, int ldc)
{
    extern __shared__ char smem[];
    const uint32_t sbase = smem_u32(smem);

    const int tid = threadIdx.x;
    const int wid = tid >> 5;
    const int lane = tid & 31;
    const int m0 = blockIdx.y * 128;
    const int n0 = blockIdx.x * 128;
    const int warp_m = (wid >> 2) * 64;   // 0 or 64
    const int warp_n = (wid & 3) * 32;    // 0,32,64,96

    float acc[4][4][4];
#pragma unroll
    for (int i = 0; i < 4; i++)
#pragma unroll
        for (int j = 0; j < 4; j++)
#pragma unroll
            for (int k = 0; k < 4; k++) acc[i][j][k] = 0.f;

    const int nIter = Kp >> 5;   // BK = 32

    auto load_tiles = [&](int kt, int buf) {
#pragma unroll
        for (int h = 0; h < 2; h++) {
            const int idx = tid + h * 256;
            const int row = idx >> 2;
            const int g = idx & 3;
            cp_async16(sbase + buf * TILEB + row * PITCHB + g * 16,
                       (const char*)(A + (size_t)(m0 + row) * Kp + kt) + g * 16);
        }
#pragma unroll
        for (int h = 0; h < 2; h++) {
            const int idx = tid + h * 256;
            const int row = idx >> 2;
            const int g = idx & 3;
            cp_async16(sbase + 2 * TILEB + buf * TILEB + row * PITCHB + g * 16,
                       (const char*)(B + (size_t)(n0 + row) * Kp + kt) + g * 16);
        }
        cp_commit();
    };

    load_tiles(0, 0);

    for (int i = 0; i < nIter; i++) {
        const int buf = i & 1;
        if (i + 1 < nIter) {
            load_tiles((i + 1) << 5, buf ^ 1);
            cp_wait<1>();
        } else {
            cp_wait<0>();
        }
        __syncthreads();

        const uint32_t aBase = sbase + buf * TILEB;
        const uint32_t bBase = sbase + 2 * TILEB + buf * TILEB;
#pragma unroll
        for (int ks = 0; ks < 2; ks++) {
            uint32_t afr[4][4];
#pragma unroll
            for (int mi = 0; mi < 4; mi++) {
                const uint32_t addr = aBase
                    + (warp_m + mi * 16 + (lane & 15)) * PITCHB
                    + (ks * 16 + ((lane >> 4) << 3)) * 2;
                ldm_x4(afr[mi], addr);
            }
            uint32_t bfr[4][2];
#pragma unroll
            for (int np = 0; np < 2; np++) {
                uint32_t r[4];
                const uint32_t addr = bBase
                    + (warp_n + np * 16 + ((lane >> 4) << 3) + (lane & 7)) * PITCHB
                    + (ks * 16 + (lane & 8)) * 2;
                ldm_x4(r, addr);
                bfr[np * 2 + 0][0] = r[0]; bfr[np * 2 + 0][1] = r[1];
                bfr[np * 2 + 1][0] = r[2]; bfr[np * 2 + 1][1] = r[3];
            }
#pragma unroll
            for (int mi = 0; mi < 4; mi++)
#pragma unroll
                for (int ni = 0; ni < 4; ni++)
                    mma_bf16(acc[mi][ni], afr[mi], bfr[ni]);
        }
        __syncthreads();
    }

    // epilogue
#pragma unroll
    for (int mi = 0; mi < 4; mi++) {
        const int row = m0 + warp_m + mi * 16 + (lane >> 2);
#pragma unroll
        for (int ni = 0; ni < 4; ni++) {
            const int col = n0 + warp_n + ni * 8 + (lane & 3) * 2;
            float2 v0 = make_float2(acc[mi][ni][0], acc[mi][ni][1]);
            float2 v1 = make_float2(acc[mi][ni][2], acc[mi][ni][3]);
            *(float2*)(C + (size_t)row * ldc + col) = v0;
            *(float2*)(C + (size_t)(row + 8) * ldc + col) = v1;
        }
    }
}

// ---------------------------------------------------------------------------
// bf16 split prep: A[M,Kc] fp32 -> [hi | hi | lo], B transpose+split -> [hi|lo|hi]
// ---------------------------------------------------------------------------
__global__ void splitA_kernel(const float* __restrict__ X,
                              __nv_bfloat16* __restrict__ Ao,
                              int total4, int Kc)
{
    const int t = blockIdx.x * 256 + threadIdx.x;
    if (t >= total4) return;
    const int cols4 = Kc >> 2;
    const int row = t / cols4;
    const int c = (t - row * cols4) * 4;
    const float4 v = *(const float4*)(X + (size_t)row * Kc + c);

    union { __nv_bfloat16 h[4]; uint2 u; } hi, lo;
    hi.h[0] = __float2bfloat16(v.x); lo.h[0] = __float2bfloat16(v.x - __bfloat162float(hi.h[0]));
    hi.h[1] = __float2bfloat16(v.y); lo.h[1] = __float2bfloat16(v.y - __bfloat162float(hi.h[1]));
    hi.h[2] = __float2bfloat16(v.z); lo.h[2] = __float2bfloat16(v.z - __bfloat162float(hi.h[2]));
    hi.h[3] = __float2bfloat16(v.w); lo.h[3] = __float2bfloat16(v.w - __bfloat162float(hi.h[3]));

    const size_t b = (size_t)row * 3 * Kc + c;
    *(uint2*)(Ao + b)          = hi.u;
    *(uint2*)(Ao + b + Kc)     = hi.u;
    *(uint2*)(Ao + b + 2 * Kc) = lo.u;
}

__global__ void splitTransB_kernel(const float* __restrict__ W,
                                   __nv_bfloat16* __restrict__ Bo,
                                   int K, int N)
{
    __shared__ float tile[32][33];
    const int tx = threadIdx.x & 31;
    const int ty = threadIdx.x >> 5;
    const int n0 = blockIdx.x * 32;
    const int k0 = blockIdx.y * 32;
#pragma unroll
    for (int j = 0; j < 4; j++)
        tile[ty + 8 * j][tx] = W[(size_t)(k0 + ty + 8 * j) * N + n0 + tx];
    __syncthreads();
#pragma unroll
    for (int j = 0; j < 4; j++) {
        const int n = n0 + ty + 8 * j;
        const int k = k0 + tx;
        const float v = tile[tx][ty + 8 * j];
        const __nv_bfloat16 h = __float2bfloat16(v);
        const __nv_bfloat16 l = __float2bfloat16(v - __bfloat162float(h));
        const size_t b = (size_t)n * 3 * K + k;
        Bo[b]         = h;
        Bo[b + K]     = l;
        Bo[b + 2 * K] = h;
    }
}

// ---------------------------------------------------------------------------
// fp32 SIMT GEMM for the two skinny GEMMs
// ---------------------------------------------------------------------------
template<int EPI>
__global__ void __launch_bounds__(256) sgemm128(
    const float* __restrict__ A, const float* __restrict__ B,
    float* __restrict__ C, const float* __restrict__ bias,
    int M, int N, int K, int lda, int ldb, int ldc, int kChunk)
{
    __shared__ float As[16][128];
    __shared__ float Bs[16][128];

    const int tid = threadIdx.x;
    const int m0 = blockIdx.y * 128;
    const int n0 = blockIdx.x * 128;
    const int k0 = blockIdx.z * kChunk;
    int kEnd = k0 + kChunk; if (kEnd > K) kEnd = K;

    float acc[8][8];
#pragma unroll
    for (int i = 0; i < 8; i++)
#pragma unroll
        for (int j = 0; j < 8; j++) acc[i][j] = 0.f;

    const int tr = tid >> 4;
    const int tc = tid & 15;
    const int arow = tid >> 2;
    const int acol = (tid & 3) * 4;
    const int brow = tid >> 5;
    const int bcol = (tid & 31) * 4;

    for (int kt = k0; kt < kEnd; kt += 16) {
        __syncthreads();
#pragma unroll
        for (int rr = 0; rr < 2; rr++) {
            int row = arow + rr * 64;
            const float4 v = *(const float4*)(A + (size_t)(m0 + row) * lda + kt + acol);
            As[acol + 0][row] = v.x;
            As[acol + 1][row] = v.y;
            As[acol + 2][row] = v.z;
            As[acol + 3][row] = v.w;
        }
#pragma unroll
        for (int rr = 0; rr < 2; rr++) {
            int row = brow + rr * 8;
            float4 v = make_float4(0.f, 0.f, 0.f, 0.f);
            if (n0 + bcol < N)
                v = *(const float4*)(B + (size_t)(kt + row) * ldb + n0 + bcol);
            *(float4*)&Bs[row][bcol] = v;
        }
        __syncthreads();

#pragma unroll
        for (int k = 0; k < 16; k++) {
            float a[8], b[8];
            *(float4*)&a[0] = *(const float4*)&As[k][tr * 8];
            *(float4*)&a[4] = *(const float4*)&As[k][tr * 8 + 4];
            *(float4*)&b[0] = *(const float4*)&Bs[k][tc * 8];
            *(float4*)&b[4] = *(const float4*)&Bs[k][tc * 8 + 4];
#pragma unroll
            for (int i = 0; i < 8; i++)
#pragma unroll
                for (int j = 0; j < 8; j++)
                    acc[i][j] = fmaf(a[i], b[j], acc[i][j]);
        }
    }

    const size_t zoff = (EPI == 3) ? (size_t)blockIdx.z * (size_t)M * ldc : 0;
#pragma unroll
    for (int i = 0; i < 8; i++) {
        const int row = m0 + tr * 8 + i;
#pragma unroll
        for (int jj = 0; jj < 8; jj += 4) {
            const int col = n0 + tc * 8 + jj;
            if (col < N) {
                float4 v;
                v.x = acc[i][jj + 0]; v.y = acc[i][jj + 1];
                v.z = acc[i][jj + 2]; v.w = acc[i][jj + 3];
                if (EPI == 2) {
                    const float4 bb = *(const float4*)(bias + col);
                    v.x = softplus_f(v.x + bb.x);
                    v.y = softplus_f(v.y + bb.y);
                    v.z = softplus_f(v.z + bb.z);
                    v.w = softplus_f(v.w + bb.w);
                }
                *(float4*)(C + zoff + (size_t)row * ldc + col) = v;
            }
        }
    }
}

__global__ void conv_silu_kernel(const float* __restrict__ conv_w,
                                 const float* __restrict__ conv_b)
{
    const int t = blockIdx.x * 256 + threadIdx.x;
    if (t >= MTOT * (DI / 4)) return;
    const int d4 = t & (DI / 4 - 1);
    const int r  = t >> 9;
    const int l  = r & (LL - 1);
    const int d  = d4 * 4;

    const float4 b4 = *(const float4*)(conv_b + d);
    float ax = b4.x, ay = b4.y, az = b4.z, aw = b4.w;
#pragma unroll
    for (int k = 0; k < 4; k++) {
        const int ls = l - 3 + k;
        if (ls >= 0) {
            const float4 v = *(const float4*)(g_xz + (size_t)(r - 3 + k) * (2 * DI) + d);
            ax = fmaf(v.x, conv_w[(d + 0) * 4 + k], ax);
            ay = fmaf(v.y, conv_w[(d + 1) * 4 + k], ay);
            az = fmaf(v.z, conv_w[(d + 2) * 4 + k], az);
            aw = fmaf(v.w, conv_w[(d + 3) * 4 + k], aw);
        }
    }
    float4 o;
    o.x = silu_f(ax); o.y = silu_f(ay); o.z = silu_f(az); o.w = silu_f(aw);
    *(float4*)(g_xb + (size_t)r * DI + d) = o;
}

__global__ void reduce_xdbl_kernel()
{
    const int i = blockIdx.x * 256 + threadIdx.x;
    if (i >= MTOT * XDN) return;
    float s = 0.f;
#pragma unroll
    for (int z = 0; z < SPLITK; z++)
        s += g_xdp[(size_t)z * MTOT * XDN + i];
    g_xdbl[i] = s;
}

__global__ void __launch_bounds__(256) scan_kernel(const float* __restrict__ A_log,
                                                   const float* __restrict__ Dvec)
{
    const int tid = threadIdx.x;
    const int grp = tid >> 4;
    const int n   = tid & 15;
    const int c   = blockIdx.x * 16 + grp;
    const int b   = c >> 11;
    const int d   = c & (DI - 1);

    const float a  = -__expf(A_log[d * NST + n]);
    const float Dd = Dvec[d];

    const size_t r0 = (size_t)b << 11;
    const float* dtp = g_dt   + r0 * DI + d;
    const float* xbp = g_xb   + r0 * DI + d;
    const float* zp  = g_xz   + r0 * (2 * DI) + DI + d;
    const float* bcp = g_xdbl + r0 * XDN + DTR + n;
    float*       yp  = g_yg   + r0 * DI + d;

    float h = 0.f;
    for (int l = 0; l < LL; l++) {
        const float dtv = dtp[(size_t)l * DI];
        const float xv  = xbp[(size_t)l * DI];
        const float Bn  = bcp[(size_t)l * XDN];
        const float Cn  = bcp[(size_t)l * XDN + NST];
        const float dA  = __expf(a * dtv);
        h = fmaf(h, dA, xv * dtv * Bn);
        float y = h * Cn;
        y += __shfl_xor_sync(0xffffffffu, y, 1);
        y += __shfl_xor_sync(0xffffffffu, y, 2);
        y += __shfl_xor_sync(0xffffffffu, y, 4);
        y += __shfl_xor_sync(0xffffffffu, y, 8);
        if (n == 0) {
            const float zv = zp[(size_t)l * (2 * DI)];
            yp[(size_t)l * DI] = (y + xv * Dd) * silu_f(zv);
        }
    }
}

extern "C" void kernel_launch(void* const* d_in, const int* in_sizes, int n_in,
                              void* d_out, int out_size)
{
    const float* x      = (const float*)d_in[0];
    const float* W_in   = (const float*)d_in[1];
    const float* conv_w = (const float*)d_in[2];
    const float* conv_b = (const float*)d_in[3];
    const float* W_x    = (const float*)d_in[4];
    const float* W_dt   = (const float*)d_in[5];
    const float* b_dt   = (const float*)d_in[6];
    const float* A_log  = (const float*)d_in[7];
    const float* Dv     = (const float*)d_in[8];
    const float* W_out  = (const float*)d_in[9];
    float* out = (float*)d_out;

    float *xz, *xb, *xdp, *xdbl, *dt, *yg;
    __nv_bfloat16 *a1, *b1, *a2, *b2;
    cudaGetSymbolAddress((void**)&xz,   g_xz);
    cudaGetSymbolAddress((void**)&xb,   g_xb);
    cudaGetSymbolAddress((void**)&xdp,  g_xdp);
    cudaGetSymbolAddress((void**)&xdbl, g_xdbl);
    cudaGetSymbolAddress((void**)&dt,   g_dt);
    cudaGetSymbolAddress((void**)&yg,   g_yg);
    cudaGetSymbolAddress((void**)&a1,   g_A1);
    cudaGetSymbolAddress((void**)&b1,   g_B1);
    cudaGetSymbolAddress((void**)&a2,   g_A2);
    cudaGetSymbolAddress((void**)&b2,   g_B2);

    // 1) split prep + GEMM1: xz = x @ W_in  (bf16 3-term split, mma.sync)
    splitA_kernel<<<(MTOT * DM / 4 + 255) / 256, 256>>>(x, a1, MTOT * DM / 4, DM);
    splitTransB_kernel<<<dim3((2 * DI) / 32, DM / 32), 256>>>(W_in, b1, DM, 2 * DI);
    gemm_mma<<<dim3((2 * DI) / 128, MTOT / 128), 256, 4 * TILEB>>>(a1, b1, xz, 3 * DM, 2 * DI);
    // 2) causal conv + SiLU
    conv_silu_kernel<<<(MTOT * (DI / 4)) / 256, 256>>>(conv_w, conv_b);
    // 3) x_dbl = xb @ W_x (split-K fp32) + deterministic reduce
    sgemm128<3><<<dim3(1, 32, SPLITK), 256>>>(xb, W_x, xdp, nullptr,
                                              MTOT, XDN, DI, DI, XDN, XDN, DI / SPLITK);
    reduce_xdbl_kernel<<<(MTOT * XDN + 255) / 256, 256>>>();
    // 4) dt = softplus(dt_low @ W_dt + b_dt)
    sgemm128<2><<<dim3(16, 32, 1), 256>>>(xdbl, W_dt, dt, b_dt,
                                          MTOT, DI, DTR, XDN, DI, DI, DTR);
    // 5) selective scan + gating
    scan_kernel<<<MTOT / 16, 256>>>(A_log, Dv);
    // 6) split prep + GEMM2: out = yg @ W_out
    splitA_kernel<<<(MTOT * DI / 4 + 255) / 256, 256>>>(yg, a2, MTOT * DI / 4, DI);
    splitTransB_kernel<<<dim3(DM / 32, DI / 32), 256>>>(W_out, b2, DI, DM);
    gemm_mma<<<dim3(DM / 128, MTOT / 128), 256, 4 * TILEB>>>(a2, b2, out, 3 * DI, DM);
}

// round 4
// speedup vs baseline: 1.3352x; 1.0464x over previous
#include <cuda_runtime.h>
#include <cuda_bf16.h>
#include <math.h>
#include <stdint.h>

#define BB   2
#define LL   2048
#define DM   1024
#define DI   2048
#define MTOT (BB*LL)
#define NST  16
#define DTR  64
#define XDN  96
#define SPLITK 8

__device__ float g_xz  [(size_t)MTOT * 2 * DI];
__device__ float g_xb  [(size_t)MTOT * DI];
__device__ float g_xdp [(size_t)SPLITK * MTOT * XDN];
__device__ float g_xdbl[(size_t)MTOT * XDN];
__device__ float g_dt  [(size_t)MTOT * DI];
__device__ float g_yg  [(size_t)MTOT * DI];
__device__ __nv_bfloat16 g_A1[(size_t)MTOT * 3 * DM];
__device__ __nv_bfloat16 g_B1[(size_t)(2*DI) * 3 * DM];
__device__ __nv_bfloat16 g_A2[(size_t)MTOT * 3 * DI];
__device__ __nv_bfloat16 g_B2[(size_t)DM * 3 * DI];

__device__ __forceinline__ float softplus_f(float v) {
    return v > 20.f ? v : log1pf(__expf(v));
}
__device__ __forceinline__ float silu_f(float v) {
    return v / (1.f + __expf(-v));
}

__device__ __forceinline__ uint32_t smem_u32(const void* p) {
    uint32_t addr;
    asm("{ .reg .u64 tmp; cvta.to.shared.u64 tmp, %1; cvt.u32.u64 %0, tmp; }"
        : "=r"(addr) : "l"(p));
    return addr;
}
__device__ __forceinline__ void cp_async16(uint32_t dst, const void* src) {
    asm volatile("cp.async.cg.shared.global [%0], [%1], 16;" :: "r"(dst), "l"(src));
}
__device__ __forceinline__ void cp_commit() {
    asm volatile("cp.async.commit_group;");
}
template<int N>
__device__ __forceinline__ void cp_wait() {
    asm volatile("cp.async.wait_group %0;" :: "n"(N) : "memory");
}
__device__ __forceinline__ void ldm_x4(uint32_t* r, uint32_t addr) {
    asm volatile("ldmatrix.sync.aligned.m8n8.x4.shared.b16 {%0,%1,%2,%3}, [%4];"
        : "=r"(r[0]), "=r"(r[1]), "=r"(r[2]), "=r"(r[3]) : "r"(addr));
}
__device__ __forceinline__ void mma_bf16(float* c, const uint32_t* a, const uint32_t* b) {
    asm volatile(
        "mma.sync.aligned.m16n8k16.row.col.f32.bf16.bf16.f32 "
        "{%0,%1,%2,%3}, {%4,%5,%6,%7}, {%8,%9}, {%0,%1,%2,%3};"
        : "+f"(c[0]), "+f"(c[1]), "+f"(c[2]), "+f"(c[3])
        : "r"(a[0]), "r"(a[1]), "r"(a[2]), "r"(a[3]), "r"(b[0]), "r"(b[1]));
}

// ---------------------------------------------------------------------------
// bf16 mma.sync GEMM: C[M,N] = A[M,Kp] * B[N,Kp]^T, fp32 accumulate.
// 128x128x32 block tile, 8 warps (2x4), 64x32 warp tiles.
// 3-stage cp.async pipeline, ONE __syncthreads per iteration, empty-group
// commits keep wait_group<1> aligned at the tail.
// Dynamic smem = 3 * 20480 = 61440 B.
// ---------------------------------------------------------------------------
#define PITCHB 80          // bytes per smem row (32 bf16 + 8 pad)
#define TILEB  10240       // 128 rows * 80 B
#define STAGEB (2*TILEB)   // A tile + B tile per stage
#define NSTAGE 3
__global__ void __launch_bounds__(256, 2) gemm_mma(
    const __nv_bfloat16* __restrict__ A, const __nv_bfloat16* __restrict__ B,
    float* __restrict__ C, int Kp, int ldc)
{
    extern __shared__ char smem[];
    const uint32_t sbase = smem_u32(smem);

    const int tid = threadIdx.x;
    const int wid = tid >> 5;
    const int lane = tid & 31;
    const int m0 = blockIdx.y * 128;
    const int n0 = blockIdx.x * 128;
    const int warp_m = (wid >> 2) * 64;
    const int warp_n = (wid & 3) * 32;

    float acc[4][4][4];
#pragma unroll
    for (int i = 0; i < 4; i++)
#pragma unroll
        for (int j = 0; j < 4; j++)
#pragma unroll
            for (int k = 0; k < 4; k++) acc[i][j][k] = 0.f;

    const int nIter = Kp >> 5;   // BK = 32

    // per-thread load coords (2 rows A + 2 rows B per thread)
    const int lrow = tid >> 2;          // 0..63
    const int lg = tid & 3;             // 16B granule
    const __nv_bfloat16* aSrc0 = A + (size_t)(m0 + lrow) * Kp + lg * 8;
    const __nv_bfloat16* aSrc1 = A + (size_t)(m0 + lrow + 64) * Kp + lg * 8;
    const __nv_bfloat16* bSrc0 = B + (size_t)(n0 + lrow) * Kp + lg * 8;
    const __nv_bfloat16* bSrc1 = B + (size_t)(n0 + lrow + 64) * Kp + lg * 8;
    const uint32_t aDst0 = sbase + lrow * PITCHB + lg * 16;
    const uint32_t aDst1 = sbase + (lrow + 64) * PITCHB + lg * 16;
    const uint32_t bDst0 = sbase + TILEB + lrow * PITCHB + lg * 16;
    const uint32_t bDst1 = sbase + TILEB + (lrow + 64) * PITCHB + lg * 16;

    auto load_stage = [&](int i, int buf) {
        const int kt = i << 5;
        const uint32_t so = buf * STAGEB;
        cp_async16(aDst0 + so, aSrc0 + kt);
        cp_async16(aDst1 + so, aSrc1 + kt);
        cp_async16(bDst0 + so, bSrc0 + kt);
        cp_async16(bDst1 + so, bSrc1 + kt);
    };

    // prologue: stages 0 and 1
    load_stage(0, 0); cp_commit();
    load_stage(1, 1); cp_commit();

    int buf = 0;
    for (int i = 0; i < nIter; i++) {
        cp_wait<1>();          // group i complete (groups are committed every iter)
        __syncthreads();

        // issue stage i+2 into the buffer freed by compute(i-1)
        if (i + 2 < nIter) {
            int nb = buf + 2; if (nb >= NSTAGE) nb -= NSTAGE;
            load_stage(i + 2, nb);
        }
        cp_commit();           // ALWAYS commit (possibly empty) to keep indices aligned

        const uint32_t aBase = sbase + buf * STAGEB;
        const uint32_t bBase = aBase + TILEB;
#pragma unroll
        for (int ks = 0; ks < 2; ks++) {
            uint32_t afr[4][4];
#pragma unroll
            for (int mi = 0; mi < 4; mi++) {
                const uint32_t addr = aBase
                    + (warp_m + mi * 16 + (lane & 15)) * PITCHB
                    + (ks * 16 + ((lane >> 4) << 3)) * 2;
                ldm_x4(afr[mi], addr);
            }
            uint32_t bfr[4][2];
#pragma unroll
            for (int np = 0; np < 2; np++) {
                uint32_t r[4];
                const uint32_t addr = bBase
                    + (warp_n + np * 16 + ((lane >> 4) << 3) + (lane & 7)) * PITCHB
                    + (ks * 16 + (lane & 8)) * 2;
                ldm_x4(r, addr);
                bfr[np * 2 + 0][0] = r[0]; bfr[np * 2 + 0][1] = r[1];
                bfr[np * 2 + 1][0] = r[2]; bfr[np * 2 + 1][1] = r[3];
            }
#pragma unroll
            for (int mi = 0; mi < 4; mi++)
#pragma unroll
                for (int ni = 0; ni < 4; ni++)
                    mma_bf16(acc[mi][ni], afr[mi], bfr[ni]);
        }
        buf++; if (buf == NSTAGE) buf = 0;
    }

    // epilogue
#pragma unroll
    for (int mi = 0; mi < 4; mi++) {
        const int row = m0 + warp_m + mi * 16 + (lane >> 2);
#pragma unroll
        for (int ni = 0; ni < 4; ni++) {
            const int col = n0 + warp_n + ni * 8 + (lane & 3) * 2;
            float2 v0 = make_float2(acc[mi][ni][0], acc[mi][ni][1]);
            float2 v1 = make_float2(acc[mi][ni][2], acc[mi][ni][3]);
            *(float2*)(C + (size_t)row * ldc + col) = v0;
            *(float2*)(C + (size_t)(row + 8) * ldc + col) = v1;
        }
    }
}

// ---------------------------------------------------------------------------
// bf16 split prep
// ---------------------------------------------------------------------------
__global__ void splitA_kernel(const float* __restrict__ X,
                              __nv_bfloat16* __restrict__ Ao,
                              int total4, int Kc)
{
    const int t = blockIdx.x * 256 + threadIdx.x;
    if (t >= total4) return;
    const int cols4 = Kc >> 2;
    const int row = t / cols4;
    const int c = (t - row * cols4) * 4;
    const float4 v = *(const float4*)(X + (size_t)row * Kc + c);

    union { __nv_bfloat16 h[4]; uint2 u; } hi, lo;
    hi.h[0] = __float2bfloat16(v.x); lo.h[0] = __float2bfloat16(v.x - __bfloat162float(hi.h[0]));
    hi.h[1] = __float2bfloat16(v.y); lo.h[1] = __float2bfloat16(v.y - __bfloat162float(hi.h[1]));
    hi.h[2] = __float2bfloat16(v.z); lo.h[2] = __float2bfloat16(v.z - __bfloat162float(hi.h[2]));
    hi.h[3] = __float2bfloat16(v.w); lo.h[3] = __float2bfloat16(v.w - __bfloat162float(hi.h[3]));

    const size_t b = (size_t)row * 3 * Kc + c;
    *(uint2*)(Ao + b)          = hi.u;
    *(uint2*)(Ao + b + Kc)     = hi.u;
    *(uint2*)(Ao + b + 2 * Kc) = lo.u;
}

__global__ void splitTransB_kernel(const float* __restrict__ W,
                                   __nv_bfloat16* __restrict__ Bo,
                                   int K, int N)
{
    __shared__ float tile[32][33];
    const int tx = threadIdx.x & 31;
    const int ty = threadIdx.x >> 5;
    const int n0 = blockIdx.x * 32;
    const int k0 = blockIdx.y * 32;
#pragma unroll
    for (int j = 0; j < 4; j++)
        tile[ty + 8 * j][tx] = W[(size_t)(k0 + ty + 8 * j) * N + n0 + tx];
    __syncthreads();
#pragma unroll
    for (int j = 0; j < 4; j++) {
        const int n = n0 + ty + 8 * j;
        const int k = k0 + tx;
        const float v = tile[tx][ty + 8 * j];
        const __nv_bfloat16 h = __float2bfloat16(v);
        const __nv_bfloat16 l = __float2bfloat16(v - __bfloat162float(h));
        const size_t b = (size_t)n * 3 * K + k;
        Bo[b]         = h;
        Bo[b + K]     = l;
        Bo[b + 2 * K] = h;
    }
}

// ---------------------------------------------------------------------------
// fp32 SIMT GEMM for the two skinny GEMMs
// ---------------------------------------------------------------------------
template<int EPI>
__global__ void __launch_bounds__(256) sgemm128(
    const float* __restrict__ A, const float* __restrict__ B,
    float* __restrict__ C, const float* __restrict__ bias,
    int M, int N, int K, int lda, int ldb, int ldc, int kChunk)
{
    __shared__ float As[16][128];
    __shared__ float Bs[16][128];

    const int tid = threadIdx.x;
    const int m0 = blockIdx.y * 128;
    const int n0 = blockIdx.x * 128;
    const int k0 = blockIdx.z * kChunk;
    int kEnd = k0 + kChunk; if (kEnd > K) kEnd = K;

    float acc[8][8];
#pragma unroll
    for (int i = 0; i < 8; i++)
#pragma unroll
        for (int j = 0; j < 8; j++) acc[i][j] = 0.f;

    const int tr = tid >> 4;
    const int tc = tid & 15;
    const int arow = tid >> 2;
    const int acol = (tid & 3) * 4;
    const int brow = tid >> 5;
    const int bcol = (tid & 31) * 4;

    for (int kt = k0; kt < kEnd; kt += 16) {
        __syncthreads();
#pragma unroll
        for (int rr = 0; rr < 2; rr++) {
            int row = arow + rr * 64;
            const float4 v = *(const float4*)(A + (size_t)(m0 + row) * lda + kt + acol);
            As[acol + 0][row] = v.x;
            As[acol + 1][row] = v.y;
            As[acol + 2][row] = v.z;
            As[acol + 3][row] = v.w;
        }
#pragma unroll
        for (int rr = 0; rr < 2; rr++) {
            int row = brow + rr * 8;
            float4 v = make_float4(0.f, 0.f, 0.f, 0.f);
            if (n0 + bcol < N)
                v = *(const float4*)(B + (size_t)(kt + row) * ldb + n0 + bcol);
            *(float4*)&Bs[row][bcol] = v;
        }
        __syncthreads();

#pragma unroll
        for (int k = 0; k < 16; k++) {
            float a[8], b[8];
            *(float4*)&a[0] = *(const float4*)&As[k][tr * 8];
            *(float4*)&a[4] = *(const float4*)&As[k][tr * 8 + 4];
            *(float4*)&b[0] = *(const float4*)&Bs[k][tc * 8];
            *(float4*)&b[4] = *(const float4*)&Bs[k][tc * 8 + 4];
#pragma unroll
            for (int i = 0; i < 8; i++)
#pragma unroll
                for (int j = 0; j < 8; j++)
                    acc[i][j] = fmaf(a[i], b[j], acc[i][j]);
        }
    }

    const size_t zoff = (EPI == 3) ? (size_t)blockIdx.z * (size_t)M * ldc : 0;
#pragma unroll
    for (int i = 0; i < 8; i++) {
        const int row = m0 + tr * 8 + i;
#pragma unroll
        for (int jj = 0; jj < 8; jj += 4) {
            const int col = n0 + tc * 8 + jj;
            if (col < N) {
                float4 v;
                v.x = acc[i][jj + 0]; v.y = acc[i][jj + 1];
                v.z = acc[i][jj + 2]; v.w = acc[i][jj + 3];
                if (EPI == 2) {
                    const float4 bb = *(const float4*)(bias + col);
                    v.x = softplus_f(v.x + bb.x);
                    v.y = softplus_f(v.y + bb.y);
                    v.z = softplus_f(v.z + bb.z);
                    v.w = softplus_f(v.w + bb.w);
                }
                *(float4*)(C + zoff + (size_t)row * ldc + col) = v;
            }
        }
    }
}

// ---------------------------------------------------------------------------
// Causal depthwise conv (k=4) + bias + SiLU.
// 8 consecutive l-positions per thread with a rolling 4-row register window:
// 11 row-loads per 8 outputs (vs 32) -> ~2.9x fewer L1 wavefronts.
// ---------------------------------------------------------------------------
__global__ void conv_silu_kernel(const float* __restrict__ conv_w,
                                 const float* __restrict__ conv_b)
{
    const int t = blockIdx.x * 256 + threadIdx.x;        // (MTOT/8)*(DI/4) threads
    const int d4 = t & (DI / 4 - 1);
    const int lb = t >> 9;                               // 0..511
    const int d = d4 * 4;
    const int l0 = lb * 8;                               // global row base
    const int lmod = l0 & (LL - 1);                      // position within batch

    const float4 w0 = *(const float4*)(conv_w + (d + 0) * 4);
    const float4 w1 = *(const float4*)(conv_w + (d + 1) * 4);
    const float4 w2 = *(const float4*)(conv_w + (d + 2) * 4);
    const float4 w3 = *(const float4*)(conv_w + (d + 3) * 4);
    const float4 bi = *(const float4*)(conv_b + d);

    const float* src = g_xz + (size_t)l0 * (2 * DI) + d;
    float* dst = g_xb + (size_t)l0 * DI + d;

    float4 h0, h1, h2;   // rows l-3, l-2, l-1
    if (lmod == 0) {
        h0 = make_float4(0.f, 0.f, 0.f, 0.f);
        h1 = h0; h2 = h0;
    } else {
        h0 = *(const float4*)(src - 3 * (size_t)(2 * DI));
        h1 = *(const float4*)(src - 2 * (size_t)(2 * DI));
        h2 = *(const float4*)(src - 1 * (size_t)(2 * DI));
    }

#pragma unroll
    for (int j = 0; j < 8; j++) {
        const float4 cu = *(const float4*)(src + (size_t)j * (2 * DI));
        float4 o;
        o.x = bi.x + h0.x * w0.x + h1.x * w0.y + h2.x * w0.z + cu.x * w0.w;
        o.y = bi.y + h0.y * w1.x + h1.y * w1.y + h2.y * w1.z + cu.y * w1.w;
        o.z = bi.z + h0.z * w2.x + h1.z * w2.y + h2.z * w2.z + cu.z * w2.w;
        o.w = bi.w + h0.w * w3.x + h1.w * w3.y + h2.w * w3.z + cu.w * w3.w;
        o.x = silu_f(o.x); o.y = silu_f(o.y); o.z = silu_f(o.z); o.w = silu_f(o.w);
        *(float4*)(dst + (size_t)j * DI) = o;
        h0 = h1; h1 = h2; h2 = cu;
    }
}

__global__ void reduce_xdbl_kernel()
{
    const int i = blockIdx.x * 256 + threadIdx.x;
    if (i >= MTOT * XDN) return;
    float s = 0.f;
#pragma unroll
    for (int z = 0; z < SPLITK; z++)
        s += g_xdp[(size_t)z * MTOT * XDN + i];
    g_xdbl[i] = s;
}

__global__ void __launch_bounds__(256) scan_kernel(const float* __restrict__ A_log,
                                                   const float* __restrict__ Dvec)
{
    const int tid = threadIdx.x;
    const int grp = tid >> 4;
    const int n   = tid & 15;
    const int c   = blockIdx.x * 16 + grp;
    const int b   = c >> 11;
    const int d   = c & (DI - 1);

    const float a  = -__expf(A_log[d * NST + n]);
    const float Dd = Dvec[d];

    const size_t r0 = (size_t)b << 11;
    const float* dtp = g_dt   + r0 * DI + d;
    const float* xbp = g_xb   + r0 * DI + d;
    const float* zp  = g_xz   + r0 * (2 * DI) + DI + d;
    const float* bcp = g_xdbl + r0 * XDN + DTR + n;
    float*       yp  = g_yg   + r0 * DI + d;

    float h = 0.f;
    for (int l = 0; l < LL; l++) {
        const float dtv = dtp[(size_t)l * DI];
        const float xv  = xbp[(size_t)l * DI];
        const float Bn  = bcp[(size_t)l * XDN];
        const float Cn  = bcp[(size_t)l * XDN + NST];
        const float dA  = __expf(a * dtv);
        h = fmaf(h, dA, xv * dtv * Bn);
        float y = h * Cn;
        y += __shfl_xor_sync(0xffffffffu, y, 1);
        y += __shfl_xor_sync(0xffffffffu, y, 2);
        y += __shfl_xor_sync(0xffffffffu, y, 4);
        y += __shfl_xor_sync(0xffffffffu, y, 8);
        if (n == 0) {
            const float zv = zp[(size_t)l * (2 * DI)];
            yp[(size_t)l * DI] = (y + xv * Dd) * silu_f(zv);
        }
    }
}

extern "C" void kernel_launch(void* const* d_in, const int* in_sizes, int n_in,
                              void* d_out, int out_size)
{
    const float* x      = (const float*)d_in[0];
    const float* W_in   = (const float*)d_in[1];
    const float* conv_w = (const float*)d_in[2];
    const float* conv_b = (const float*)d_in[3];
    const float* W_x    = (const float*)d_in[4];
    const float* W_dt   = (const float*)d_in[5];
    const float* b_dt   = (const float*)d_in[6];
    const float* A_log  = (const float*)d_in[7];
    const float* Dv     = (const float*)d_in[8];
    const float* W_out  = (const float*)d_in[9];
    float* out = (float*)d_out;

    float *xz, *xb, *xdp, *xdbl, *dt, *yg;
    __nv_bfloat16 *a1, *b1, *a2, *b2;
    cudaGetSymbolAddress((void**)&xz,   g_xz);
    cudaGetSymbolAddress((void**)&xb,   g_xb);
    cudaGetSymbolAddress((void**)&xdp,  g_xdp);
    cudaGetSymbolAddress((void**)&xdbl, g_xdbl);
    cudaGetSymbolAddress((void**)&dt,   g_dt);
    cudaGetSymbolAddress((void**)&yg,   g_yg);
    cudaGetSymbolAddress((void**)&a1,   g_A1);
    cudaGetSymbolAddress((void**)&b1,   g_B1);
    cudaGetSymbolAddress((void**)&a2,   g_A2);
    cudaGetSymbolAddress((void**)&b2,   g_B2);

    cudaFuncSetAttribute(gemm_mma, cudaFuncAttributeMaxDynamicSharedMemorySize,
                         NSTAGE * STAGEB);

    // 1) split prep + GEMM1: xz = x @ W_in
    splitA_kernel<<<(MTOT * DM / 4 + 255) / 256, 256>>>(x, a1, MTOT * DM / 4, DM);
    splitTransB_kernel<<<dim3((2 * DI) / 32, DM / 32), 256>>>(W_in, b1, DM, 2 * DI);
    gemm_mma<<<dim3((2 * DI) / 128, MTOT / 128), 256, NSTAGE * STAGEB>>>(a1, b1, xz, 3 * DM, 2 * DI);
    // 2) causal conv + SiLU
    conv_silu_kernel<<<(MTOT / 8) * (DI / 4) / 256, 256>>>(conv_w, conv_b);
    // 3) x_dbl = xb @ W_x (split-K fp32) + deterministic reduce
    sgemm128<3><<<dim3(1, 32, SPLITK), 256>>>(xb, W_x, xdp, nullptr,
                                              MTOT, XDN, DI, DI, XDN, XDN, DI / SPLITK);
    reduce_xdbl_kernel<<<(MTOT * XDN + 255) / 256, 256>>>();
    // 4) dt = softplus(dt_low @ W_dt + b_dt)
    sgemm128<2><<<dim3(16, 32, 1), 256>>>(xdbl, W_dt, dt, b_dt,
                                          MTOT, DI, DTR, XDN, DI, DI, DTR);
    // 5) selective scan + gating
    scan_kernel<<<MTOT / 16, 256>>>(A_log, Dv);
    // 6) split prep + GEMM2: out = yg @ W_out
    splitA_kernel<<<(MTOT * DI / 4 + 255) / 256, 256>>>(yg, a2, MTOT * DI / 4, DI);
    splitTransB_kernel<<<dim3(DM / 32, DI / 32), 256>>>(W_out, b2, DI, DM);
    gemm_mma<<<dim3(DM / 128, MTOT / 128), 256, NSTAGE * STAGEB>>>(a2, b2, out, 3 * DI, DM);
}